// round 9
// baseline (speedup 1.0000x reference)
#include <cuda_runtime.h>
#include <cuda_fp16.h>
#include <math_constants.h>
#include <cstdint>

// ---------------------------------------------------------------------------
// Problem constants
// ---------------------------------------------------------------------------
#define N_ROWS 32768
#define DDIM   128
#define KCODE  1024
#define NDTOT  (N_ROWS * DDIM)   // 4194304

// scratch (no cudaMalloc allowed)
__device__ __align__(16) __half g_x_hi[NDTOT];
__device__ __align__(16) __half g_x_lo[NDTOT];
__device__ __align__(16) __half g_e_hi[KCODE * DDIM];
__device__ __align__(16) __half g_e_lo[KCODE * DDIM];
__device__ float        g_xsq[N_ROWS];
__device__ float        g_esq[KCODE];
__device__ int          g_idx[N_ROWS];
__device__ double       g_part[1024];
__device__ unsigned int g_done;

// ---------------------------------------------------------------------------
// helpers
// ---------------------------------------------------------------------------
__device__ __forceinline__ uint32_t smem_to_u32(const void* p) {
    uint32_t a;
    asm("{ .reg .u64 t; cvta.to.shared.u64 t, %1; cvt.u32.u64 %0, t; }"
        : "=r"(a) : "l"(p));
    return a;
}

__device__ __forceinline__ void ldsm4(uint32_t* r, uint32_t addr) {
    asm volatile("ldmatrix.sync.aligned.m8n8.x4.shared.b16 {%0,%1,%2,%3}, [%4];"
                 : "=r"(r[0]), "=r"(r[1]), "=r"(r[2]), "=r"(r[3]) : "r"(addr));
}

__device__ __forceinline__ void mma16816(float* d, const uint32_t* a,
                                         const uint32_t* b) {
    asm volatile(
        "mma.sync.aligned.m16n8k16.row.col.f32.f16.f16.f32 "
        "{%0,%1,%2,%3}, {%4,%5,%6,%7}, {%8,%9}, {%0,%1,%2,%3};"
        : "+f"(d[0]), "+f"(d[1]), "+f"(d[2]), "+f"(d[3])
        : "r"(a[0]), "r"(a[1]), "r"(a[2]), "r"(a[3]), "r"(b[0]), "r"(b[1]));
}

// cp.async a [rows x 128 half] tile into padded smem (row stride 272B)
#define STRB 272
__device__ __forceinline__ void load_tile_pad(uint32_t dst,
                                              const __half* __restrict__ g,
                                              int rows, int t, int nt) {
    for (int c = t; c < rows * 16; c += nt) {
        int r = c >> 4, ch = c & 15;
        uint32_t d = dst + (uint32_t)r * STRB + ch * 16;
        const void* s = (const void*)(g + (size_t)r * 128 + ch * 8);
        asm volatile("cp.async.cg.shared.global [%0], [%1], 16;"
                     :: "r"(d), "l"(s) : "memory");
    }
}

// smem layout (bytes):
//   A hi [128x128h pad] @ 0       (34816)
//   A lo                @ 34816   (34816)
//   B stage s (hi+lo)   @ 69632 + s*17408   (2 stages x (32 codes: 8704 hi + 8704 lo))
//   esq                 @ 104448  (4096)
#define SA_HI   0
#define SA_LO   34816
#define SB      69632
#define SB_STAGE 17408
#define SB_LO   8704
#define SESQ    104448
#define SMEM_TOTAL 108544   // x2 CTAs = 217088 <= 227KB/SM

// ---------------------------------------------------------------------------
// e_sq (order-insensitive; magnitude ~4e-5 vs d2 ~128)
// ---------------------------------------------------------------------------
__global__ void esq_kernel(const float* __restrict__ emb) {
    int warp = (blockIdx.x * blockDim.x + threadIdx.x) >> 5;
    int lane = threadIdx.x & 31;
    if (warp < KCODE) {
        float4 v = *(const float4*)&emb[(size_t)warp * DDIM + lane * 4];
        float s = v.x * v.x + v.y * v.y + v.z * v.z + v.w * v.w;
        #pragma unroll
        for (int o = 16; o > 0; o >>= 1)
            s += __shfl_xor_sync(0xffffffffu, s, o);
        if (lane == 0) g_esq[warp] = s;
    }
}

// emb -> scaled fp16 split (e*512 exact; hi + lo residual)
__global__ void convert_emb_kernel(const float* __restrict__ emb) {
    int i = blockIdx.x * blockDim.x + threadIdx.x;
    if (i < KCODE * DDIM) {
        float es = emb[i] * 512.0f;
        __half h = __float2half_rn(es);
        g_e_hi[i] = h;
        g_e_lo[i] = __float2half_rn(__fsub_rn(es, __half2float(h)));
    }
}

// x -> fp16 split + per-row x_sq (serial ascending-d, matches R3)
__global__ __launch_bounds__(256)
void convert_x_kernel(const float* __restrict__ x) {
    __shared__ float xs[64 * 132];
    const int rb = blockIdx.x * 64;
    const float4* xg = (const float4*)(x + (size_t)rb * DDIM);
    for (int t = threadIdx.x; t < 64 * 32; t += 256) {
        int r = t >> 5, c = t & 31;
        *(float4*)&xs[r * 132 + c * 4] = xg[r * 32 + c];
    }
    __syncthreads();
    if (threadIdx.x < 64) {
        const float* row = &xs[threadIdx.x * 132];
        float s = 0.0f;
        #pragma unroll 8
        for (int d = 0; d < DDIM; ++d)
            s = __fadd_rn(s, __fmul_rn(row[d], row[d]));
        g_xsq[rb + threadIdx.x] = s;
    }
    for (int i = threadIdx.x; i < 64 * DDIM; i += 256) {
        int r = i >> 7, c = i & 127;
        float v = xs[r * 132 + c];
        __half h = __float2half_rn(v);
        size_t gi = (size_t)(rb + r) * DDIM + c;
        g_x_hi[gi] = h;
        g_x_lo[gi] = __float2half_rn(__fsub_rn(v, __half2float(h)));
    }
}

// ---------------------------------------------------------------------------
// Main: HMMA distance GEMM + per-row argmin.
// 256 CTAs x 128 threads, 2 CTAs/SM. CTA = 128 rows x 1024 codes (32 N-tiles
// of 32). Warp owns 32 rows x all 32 cols. K=128 in 8 k-steps of m16n8k16.
// 3 terms (hh, hl, lh) -> acc = 512*dot, fp32 accum.
// MMA issue order: term-outer, accumulator-inner -> consecutive writes to the
// same accumulator are 8 independent MMAs apart (covers HMMA latency; the
// per-accumulator addend order hh,hl,lh per k-step is unchanged -> results
// bit-identical to R7).
// ---------------------------------------------------------------------------
__global__ __launch_bounds__(128, 2)
void vq_argmin_mma(float* __restrict__ out)
{
    extern __shared__ __align__(16) char smem[];
    const uint32_t sb = smem_to_u32(smem);
    const int tid  = threadIdx.x;
    const int lane = tid & 31;
    const int wm   = tid >> 5;   // warp id = M quadrant (32 rows)
    const int gID  = lane >> 2;
    const int tig  = lane & 3;
    const int rbase = blockIdx.x * 128;

    float* esq_s = (float*)(smem + SESQ);
    for (int i = tid; i < KCODE; i += 128) esq_s[i] = g_esq[i];

    // prologue: group0 = A hi/lo + B stage0 (codes 0..31); group1 = B stage1
    load_tile_pad(sb + SA_HI, g_x_hi + (size_t)rbase * DDIM, 128, tid, 128);
    load_tile_pad(sb + SA_LO, g_x_lo + (size_t)rbase * DDIM, 128, tid, 128);
    load_tile_pad(sb + SB,           g_e_hi, 32, tid, 128);
    load_tile_pad(sb + SB + SB_LO,   g_e_lo, 32, tid, 128);
    asm volatile("cp.async.commit_group;" ::: "memory");
    load_tile_pad(sb + SB + SB_STAGE,         g_e_hi + 32 * DDIM, 32, tid, 128);
    load_tile_pad(sb + SB + SB_STAGE + SB_LO, g_e_lo + 32 * DDIM, 32, tid, 128);
    asm volatile("cp.async.commit_group;" ::: "memory");

    // per-lane xsq for its 4 rows
    float xsq[2][2];
    #pragma unroll
    for (int mf = 0; mf < 2; ++mf)
        #pragma unroll
        for (int h = 0; h < 2; ++h)
            xsq[mf][h] = g_xsq[rbase + wm * 32 + mf * 16 + gID + h * 8];

    float bestv[2][2];
    int   bestk[2][2];
    #pragma unroll
    for (int mf = 0; mf < 2; ++mf)
        #pragma unroll
        for (int h = 0; h < 2; ++h) { bestv[mf][h] = CUDART_INF_F; bestk[mf][h] = 0; }

    // lane-dependent ldmatrix base offsets
    const uint32_t a_off = (uint32_t)((wm * 32 + (lane & 15)) * STRB + (lane >> 4) * 16);
    const uint32_t b_off = (uint32_t)(((lane & 7) + ((lane >> 4) << 3)) * STRB
                                      + ((lane >> 3) & 1) * 16);

    for (int it = 0; it < 32; ++it) {
        asm volatile("cp.async.wait_group 1;" ::: "memory");
        __syncthreads();
        const uint32_t bs = sb + SB + (uint32_t)(it & 1) * SB_STAGE;

        float acc[2][4][4];
        #pragma unroll
        for (int mf = 0; mf < 2; ++mf)
            #pragma unroll
            for (int nf = 0; nf < 4; ++nf)
                #pragma unroll
                for (int r = 0; r < 4; ++r) acc[mf][nf][r] = 0.0f;

        #pragma unroll
        for (int ks = 0; ks < 8; ++ks) {
            uint32_t aH[2][4], aL[2][4];
            #pragma unroll
            for (int mf = 0; mf < 2; ++mf) {
                ldsm4(aH[mf], sb + SA_HI + a_off + mf * 4352 + ks * 32);
                ldsm4(aL[mf], sb + SA_LO + a_off + mf * 4352 + ks * 32);
            }
            uint32_t bH[2][4], bL[2][4];
            #pragma unroll
            for (int p = 0; p < 2; ++p) {
                uint32_t ba = bs + b_off + p * 4352 + ks * 32;
                ldsm4(bH[p], ba);
                ldsm4(bL[p], ba + SB_LO);
            }
            // term-outer, accumulator-inner: 8 independent MMAs per term block
            #pragma unroll
            for (int term = 0; term < 3; ++term) {
                const uint32_t (*A)[4] = (term == 2) ? aL : aH;
                const uint32_t (*B)[4] = (term == 1) ? bL : bH;
                #pragma unroll
                for (int mf = 0; mf < 2; ++mf)
                    #pragma unroll
                    for (int p = 0; p < 2; ++p) {
                        mma16816(acc[mf][2 * p],     A[mf], &B[p][0]);
                        mma16816(acc[mf][2 * p + 1], A[mf], &B[p][2]);
                    }
            }
        }

        // epilogue: d2 = (xsq - acc/256) + esq ; running argmin, k ascending
        #pragma unroll
        for (int mf = 0; mf < 2; ++mf)
            #pragma unroll
            for (int nf = 0; nf < 4; ++nf) {
                const int kb = it * 32 + nf * 8 + 2 * tig;
                const float* a4 = acc[mf][nf];
                float d0 = __fadd_rn(__fsub_rn(xsq[mf][0], a4[0] * 0.00390625f), esq_s[kb]);
                if (d0 < bestv[mf][0]) { bestv[mf][0] = d0; bestk[mf][0] = kb; }
                float d1 = __fadd_rn(__fsub_rn(xsq[mf][0], a4[1] * 0.00390625f), esq_s[kb + 1]);
                if (d1 < bestv[mf][0]) { bestv[mf][0] = d1; bestk[mf][0] = kb + 1; }
                float d2 = __fadd_rn(__fsub_rn(xsq[mf][1], a4[2] * 0.00390625f), esq_s[kb]);
                if (d2 < bestv[mf][1]) { bestv[mf][1] = d2; bestk[mf][1] = kb; }
                float d3 = __fadd_rn(__fsub_rn(xsq[mf][1], a4[3] * 0.00390625f), esq_s[kb + 1]);
                if (d3 < bestv[mf][1]) { bestv[mf][1] = d3; bestk[mf][1] = kb + 1; }
            }

        __syncthreads();   // all warps done reading this B stage
        if (it + 2 < 32) {
            load_tile_pad(bs,         g_e_hi + (size_t)(it + 2) * 32 * DDIM, 32, tid, 128);
            load_tile_pad(bs + SB_LO, g_e_lo + (size_t)(it + 2) * 32 * DDIM, 32, tid, 128);
        }
        asm volatile("cp.async.commit_group;" ::: "memory");
    }

    // warp owns its 32 rows entirely: lexicographic (v,k) reduce over the
    // 4-lane quad (tig) preserves first-min; lane tig==0 writes directly.
    #pragma unroll
    for (int mf = 0; mf < 2; ++mf)
        #pragma unroll
        for (int h = 0; h < 2; ++h) {
            float v = bestv[mf][h];
            int   k = bestk[mf][h];
            #pragma unroll
            for (int o = 1; o <= 2; o <<= 1) {
                float vo = __shfl_xor_sync(0xffffffffu, v, o);
                int   ko = __shfl_xor_sync(0xffffffffu, k, o);
                if (vo < v || (vo == v && ko < k)) { v = vo; k = ko; }
            }
            if (tig == 0) {
                int row = rbase + wm * 32 + mf * 16 + gID + h * 8;
                g_idx[row] = k;
                out[NDTOT + 1 + row] = (float)k;
            }
        }
}

// ---------------------------------------------------------------------------
// quantized output (gather) + fp64 MSE, loss finalized by last block
// ---------------------------------------------------------------------------
__global__ __launch_bounds__(256)
void quant_kernel(const float* __restrict__ x,
                  const float* __restrict__ emb,
                  float* __restrict__ out)
{
    __shared__ double sred[256];
    __shared__ bool last;
    const int total4 = NDTOT / 4;  // 1048576
    double s = 0.0;
    for (int p = blockIdx.x * 256 + threadIdx.x; p < total4; p += gridDim.x * 256) {
        int row = p >> 5, d4 = p & 31;
        int k = g_idx[row];
        float4 q  = *(const float4*)&emb[(size_t)k * DDIM + d4 * 4];
        float4 xv = *(const float4*)&x[(size_t)p * 4];
        ((float4*)out)[p] = q;
        float a = q.x - xv.x, b = q.y - xv.y, c = q.z - xv.z, d = q.w - xv.w;
        s += (double)a * a + (double)b * b + (double)c * c + (double)d * d;
    }
    sred[threadIdx.x] = s;
    __syncthreads();
    for (int o = 128; o > 0; o >>= 1) {
        if (threadIdx.x < o) sred[threadIdx.x] += sred[threadIdx.x + o];
        __syncthreads();
    }
    if (threadIdx.x == 0) {
        g_part[blockIdx.x] = sred[0];
        __threadfence();
        unsigned v = atomicAdd(&g_done, 1u);
        last = (v == 1023u);
    }
    __syncthreads();
    if (last) {
        double t = 0.0;
        for (int i = threadIdx.x; i < 1024; i += 256) t += g_part[i];
        sred[threadIdx.x] = t;
        __syncthreads();
        for (int o = 128; o > 0; o >>= 1) {
            if (threadIdx.x < o) sred[threadIdx.x] += sred[threadIdx.x + o];
            __syncthreads();
        }
        if (threadIdx.x == 0) {
            out[NDTOT] = (float)(1.25 * (sred[0] / (double)NDTOT));
            g_done = 0;   // reset for next graph replay
        }
    }
}

// ---------------------------------------------------------------------------
extern "C" void kernel_launch(void* const* d_in, const int* in_sizes, int n_in,
                              void* d_out, int out_size)
{
    const float* x   = (const float*)d_in[0];
    const float* emb = (const float*)d_in[1];
    float* out = (float*)d_out;

    cudaFuncSetAttribute(vq_argmin_mma,
                         cudaFuncAttributeMaxDynamicSharedMemorySize, SMEM_TOTAL);

    esq_kernel<<<KCODE / 8, 256>>>(emb);
    convert_emb_kernel<<<(KCODE * DDIM + 255) / 256, 256>>>(emb);
    convert_x_kernel<<<N_ROWS / 64, 256>>>(x);
    vq_argmin_mma<<<N_ROWS / 128, 128, SMEM_TOTAL>>>(out);
    quant_kernel<<<1024, 256>>>(x, emb, out);
}

// round 11
// speedup vs baseline: 1.0162x; 1.0162x over previous
#include <cuda_runtime.h>
#include <cuda_fp16.h>
#include <math_constants.h>
#include <cstdint>

// ---------------------------------------------------------------------------
// Problem constants
// ---------------------------------------------------------------------------
#define N_ROWS 32768
#define DDIM   128
#define KCODE  1024
#define NDTOT  (N_ROWS * DDIM)   // 4194304

// scratch (no cudaMalloc allowed)
__device__ __align__(16) __half g_x_hi[NDTOT];
__device__ __align__(16) __half g_x_lo[NDTOT];
__device__ __align__(16) __half g_e_hi[KCODE * DDIM];
__device__ __align__(16) __half g_e_lo[KCODE * DDIM];
__device__ float        g_xsq[N_ROWS];
__device__ float        g_esq[KCODE];
__device__ int          g_idx[N_ROWS];
__device__ double       g_part[1024];
__device__ unsigned int g_done;

// ---------------------------------------------------------------------------
// helpers
// ---------------------------------------------------------------------------
__device__ __forceinline__ uint32_t smem_to_u32(const void* p) {
    uint32_t a;
    asm("{ .reg .u64 t; cvta.to.shared.u64 t, %1; cvt.u32.u64 %0, t; }"
        : "=r"(a) : "l"(p));
    return a;
}

__device__ __forceinline__ void ldsm4(uint32_t* r, uint32_t addr) {
    asm volatile("ldmatrix.sync.aligned.m8n8.x4.shared.b16 {%0,%1,%2,%3}, [%4];"
                 : "=r"(r[0]), "=r"(r[1]), "=r"(r[2]), "=r"(r[3]) : "r"(addr));
}

__device__ __forceinline__ void mma16816(float* d, const uint32_t* a,
                                         const uint32_t* b) {
    asm volatile(
        "mma.sync.aligned.m16n8k16.row.col.f32.f16.f16.f32 "
        "{%0,%1,%2,%3}, {%4,%5,%6,%7}, {%8,%9}, {%0,%1,%2,%3};"
        : "+f"(d[0]), "+f"(d[1]), "+f"(d[2]), "+f"(d[3])
        : "r"(a[0]), "r"(a[1]), "r"(a[2]), "r"(a[3]), "r"(b[0]), "r"(b[1]));
}

// cp.async a [rows x 128 half] tile into padded smem (row stride 272B)
#define STRB 272
__device__ __forceinline__ void load_tile_pad(uint32_t dst,
                                              const __half* __restrict__ g,
                                              int rows, int t, int nt) {
    for (int c = t; c < rows * 16; c += nt) {
        int r = c >> 4, ch = c & 15;
        uint32_t d = dst + (uint32_t)r * STRB + ch * 16;
        const void* s = (const void*)(g + (size_t)r * 128 + ch * 8);
        asm volatile("cp.async.cg.shared.global [%0], [%1], 16;"
                     :: "r"(d), "l"(s) : "memory");
    }
}

// smem layout (bytes):
//   A hi [128x128h pad] @ 0       (34816)
//   A lo                @ 34816   (34816)
//   B stage s (hi+lo)   @ 69632 + s*17408   (2 stages x (32 codes: 8704 hi + 8704 lo))
//   esq                 @ 104448  (4096)
#define SA_HI   0
#define SA_LO   34816
#define SB      69632
#define SB_STAGE 17408
#define SB_LO   8704
#define SESQ    104448
#define SMEM_TOTAL 108544   // x2 CTAs = 217088 <= 227KB/SM

// ---------------------------------------------------------------------------
// e_sq (order-insensitive; magnitude ~4e-5 vs d2 ~128)
// ---------------------------------------------------------------------------
__global__ void esq_kernel(const float* __restrict__ emb) {
    int warp = (blockIdx.x * blockDim.x + threadIdx.x) >> 5;
    int lane = threadIdx.x & 31;
    if (warp < KCODE) {
        float4 v = *(const float4*)&emb[(size_t)warp * DDIM + lane * 4];
        float s = v.x * v.x + v.y * v.y + v.z * v.z + v.w * v.w;
        #pragma unroll
        for (int o = 16; o > 0; o >>= 1)
            s += __shfl_xor_sync(0xffffffffu, s, o);
        if (lane == 0) g_esq[warp] = s;
    }
}

// emb -> scaled fp16 split (e*512 exact; hi + lo residual)
__global__ void convert_emb_kernel(const float* __restrict__ emb) {
    int i = blockIdx.x * blockDim.x + threadIdx.x;
    if (i < KCODE * DDIM) {
        float es = emb[i] * 512.0f;
        __half h = __float2half_rn(es);
        g_e_hi[i] = h;
        g_e_lo[i] = __float2half_rn(__fsub_rn(es, __half2float(h)));
    }
}

// x -> fp16 split + per-row x_sq (serial ascending-d, matches R3)
__global__ __launch_bounds__(256)
void convert_x_kernel(const float* __restrict__ x) {
    __shared__ float xs[64 * 132];
    const int rb = blockIdx.x * 64;
    const float4* xg = (const float4*)(x + (size_t)rb * DDIM);
    for (int t = threadIdx.x; t < 64 * 32; t += 256) {
        int r = t >> 5, c = t & 31;
        *(float4*)&xs[r * 132 + c * 4] = xg[r * 32 + c];
    }
    __syncthreads();
    if (threadIdx.x < 64) {
        const float* row = &xs[threadIdx.x * 132];
        float s = 0.0f;
        #pragma unroll 8
        for (int d = 0; d < DDIM; ++d)
            s = __fadd_rn(s, __fmul_rn(row[d], row[d]));
        g_xsq[rb + threadIdx.x] = s;
    }
    for (int i = threadIdx.x; i < 64 * DDIM; i += 256) {
        int r = i >> 7, c = i & 127;
        float v = xs[r * 132 + c];
        __half h = __float2half_rn(v);
        size_t gi = (size_t)(rb + r) * DDIM + c;
        g_x_hi[gi] = h;
        g_x_lo[gi] = __float2half_rn(__fsub_rn(v, __half2float(h)));
    }
}

// ---------------------------------------------------------------------------
// Main: HMMA distance GEMM + per-row argmin.
// 256 CTAs x 128 threads, 2 CTAs/SM. CTA = 128 rows x 1024 codes (32 N-tiles
// of 32). Warp owns 32 rows x all 32 cols. K=128 in 8 k-steps of m16n8k16.
// 3 terms (hh, hl, lh) -> acc = 512*dot, fp32 accum.
// R10: A-hi fragments preloaded ONCE into registers (invariant across all 32
// N-iterations; was half of all smem traffic). A-lo + B fragments stream with
// a manual ks+1 double-buffer prefetch so LDS overlaps MMA instead of
// serializing. Per-accumulator addend order (hh,hl,lh per ks, k ascending)
// unchanged -> bit-identical results.
// ---------------------------------------------------------------------------
__global__ __launch_bounds__(128, 2)
void vq_argmin_mma(float* __restrict__ out)
{
    extern __shared__ __align__(16) char smem[];
    const uint32_t sb = smem_to_u32(smem);
    const int tid  = threadIdx.x;
    const int lane = tid & 31;
    const int wm   = tid >> 5;   // warp id = M quadrant (32 rows)
    const int gID  = lane >> 2;
    const int tig  = lane & 3;
    const int rbase = blockIdx.x * 128;

    float* esq_s = (float*)(smem + SESQ);
    for (int i = tid; i < KCODE; i += 128) esq_s[i] = g_esq[i];

    // prologue: group0 = A hi/lo + B stage0 (codes 0..31); group1 = B stage1
    load_tile_pad(sb + SA_HI, g_x_hi + (size_t)rbase * DDIM, 128, tid, 128);
    load_tile_pad(sb + SA_LO, g_x_lo + (size_t)rbase * DDIM, 128, tid, 128);
    load_tile_pad(sb + SB,           g_e_hi, 32, tid, 128);
    load_tile_pad(sb + SB + SB_LO,   g_e_lo, 32, tid, 128);
    asm volatile("cp.async.commit_group;" ::: "memory");
    load_tile_pad(sb + SB + SB_STAGE,         g_e_hi + 32 * DDIM, 32, tid, 128);
    load_tile_pad(sb + SB + SB_STAGE + SB_LO, g_e_lo + 32 * DDIM, 32, tid, 128);
    asm volatile("cp.async.commit_group;" ::: "memory");

    // per-lane xsq for its 4 rows
    float xsq[2][2];
    #pragma unroll
    for (int mf = 0; mf < 2; ++mf)
        #pragma unroll
        for (int h = 0; h < 2; ++h)
            xsq[mf][h] = g_xsq[rbase + wm * 32 + mf * 16 + gID + h * 8];

    float bestv[2][2];
    int   bestk[2][2];
    #pragma unroll
    for (int mf = 0; mf < 2; ++mf)
        #pragma unroll
        for (int h = 0; h < 2; ++h) { bestv[mf][h] = CUDART_INF_F; bestk[mf][h] = 0; }

    // lane-dependent ldmatrix base offsets
    const uint32_t a_off = (uint32_t)((wm * 32 + (lane & 15)) * STRB + (lane >> 4) * 16);
    const uint32_t b_off = (uint32_t)(((lane & 7) + ((lane >> 4) << 3)) * STRB
                                      + ((lane >> 3) & 1) * 16);

    // ---- wait for A (group0), then preload ALL A-hi fragments into regs ----
    asm volatile("cp.async.wait_group 1;" ::: "memory");
    __syncthreads();
    uint32_t aHr[8][2][4];
    #pragma unroll
    for (int ks = 0; ks < 8; ++ks)
        #pragma unroll
        for (int mf = 0; mf < 2; ++mf)
            ldsm4(aHr[ks][mf], sb + SA_HI + a_off + mf * 4352 + ks * 32);

    for (int it = 0; it < 32; ++it) {
        asm volatile("cp.async.wait_group 1;" ::: "memory");
        __syncthreads();
        const uint32_t bs = sb + SB + (uint32_t)(it & 1) * SB_STAGE;

        float acc[2][4][4];
        #pragma unroll
        for (int mf = 0; mf < 2; ++mf)
            #pragma unroll
            for (int nf = 0; nf < 4; ++nf)
                #pragma unroll
                for (int r = 0; r < 4; ++r) acc[mf][nf][r] = 0.0f;

        // streamed fragments: B hi/lo + A lo, double-buffered over ks
        uint32_t bHb[2][2][4], bLb[2][2][4], aLb[2][2][4];
        {
            uint32_t ba = bs + b_off;
            ldsm4(bHb[0][0], ba);        ldsm4(bLb[0][0], ba + SB_LO);
            ldsm4(bHb[0][1], ba + 4352); ldsm4(bLb[0][1], ba + 4352 + SB_LO);
            ldsm4(aLb[0][0], sb + SA_LO + a_off);
            ldsm4(aLb[0][1], sb + SA_LO + a_off + 4352);
        }

        #pragma unroll
        for (int ks = 0; ks < 8; ++ks) {
            const int cur = ks & 1, nxt = cur ^ 1;
            if (ks < 7) {   // prefetch ks+1 fragments before issuing MMAs
                uint32_t ba = bs + b_off + (ks + 1) * 32;
                ldsm4(bHb[nxt][0], ba);        ldsm4(bLb[nxt][0], ba + SB_LO);
                ldsm4(bHb[nxt][1], ba + 4352); ldsm4(bLb[nxt][1], ba + 4352 + SB_LO);
                uint32_t aa = sb + SA_LO + a_off + (ks + 1) * 32;
                ldsm4(aLb[nxt][0], aa);
                ldsm4(aLb[nxt][1], aa + 4352);
            }
            // term 0: hh
            #pragma unroll
            for (int mf = 0; mf < 2; ++mf)
                #pragma unroll
                for (int p = 0; p < 2; ++p) {
                    mma16816(acc[mf][2 * p],     aHr[ks][mf], &bHb[cur][p][0]);
                    mma16816(acc[mf][2 * p + 1], aHr[ks][mf], &bHb[cur][p][2]);
                }
            // term 1: hl
            #pragma unroll
            for (int mf = 0; mf < 2; ++mf)
                #pragma unroll
                for (int p = 0; p < 2; ++p) {
                    mma16816(acc[mf][2 * p],     aHr[ks][mf], &bLb[cur][p][0]);
                    mma16816(acc[mf][2 * p + 1], aHr[ks][mf], &bLb[cur][p][2]);
                }
            // term 2: lh
            #pragma unroll
            for (int mf = 0; mf < 2; ++mf)
                #pragma unroll
                for (int p = 0; p < 2; ++p) {
                    mma16816(acc[mf][2 * p],     aLb[cur][mf], &bHb[cur][p][0]);
                    mma16816(acc[mf][2 * p + 1], aLb[cur][mf], &bHb[cur][p][2]);
                }
        }

        // epilogue: d2 = (xsq - acc/256) + esq ; running argmin, k ascending
        #pragma unroll
        for (int mf = 0; mf < 2; ++mf)
            #pragma unroll
            for (int nf = 0; nf < 4; ++nf) {
                const int kb = it * 32 + nf * 8 + 2 * tig;
                const float* a4 = acc[mf][nf];
                float d0 = __fadd_rn(__fsub_rn(xsq[mf][0], a4[0] * 0.00390625f), esq_s[kb]);
                if (d0 < bestv[mf][0]) { bestv[mf][0] = d0; bestk[mf][0] = kb; }
                float d1 = __fadd_rn(__fsub_rn(xsq[mf][0], a4[1] * 0.00390625f), esq_s[kb + 1]);
                if (d1 < bestv[mf][0]) { bestv[mf][0] = d1; bestk[mf][0] = kb + 1; }
                float d2 = __fadd_rn(__fsub_rn(xsq[mf][1], a4[2] * 0.00390625f), esq_s[kb]);
                if (d2 < bestv[mf][1]) { bestv[mf][1] = d2; bestk[mf][1] = kb; }
                float d3 = __fadd_rn(__fsub_rn(xsq[mf][1], a4[3] * 0.00390625f), esq_s[kb + 1]);
                if (d3 < bestv[mf][1]) { bestv[mf][1] = d3; bestk[mf][1] = kb + 1; }
            }

        __syncthreads();   // all warps done reading this B stage
        if (it + 2 < 32) {
            load_tile_pad(bs,         g_e_hi + (size_t)(it + 2) * 32 * DDIM, 32, tid, 128);
            load_tile_pad(bs + SB_LO, g_e_lo + (size_t)(it + 2) * 32 * DDIM, 32, tid, 128);
        }
        asm volatile("cp.async.commit_group;" ::: "memory");
    }

    // warp owns its 32 rows entirely: lexicographic (v,k) reduce over the
    // 4-lane quad (tig) preserves first-min; lane tig==0 writes directly.
    #pragma unroll
    for (int mf = 0; mf < 2; ++mf)
        #pragma unroll
        for (int h = 0; h < 2; ++h) {
            float v = bestv[mf][h];
            int   k = bestk[mf][h];
            #pragma unroll
            for (int o = 1; o <= 2; o <<= 1) {
                float vo = __shfl_xor_sync(0xffffffffu, v, o);
                int   ko = __shfl_xor_sync(0xffffffffu, k, o);
                if (vo < v || (vo == v && ko < k)) { v = vo; k = ko; }
            }
            if (tig == 0) {
                int row = rbase + wm * 32 + mf * 16 + gID + h * 8;
                g_idx[row] = k;
                out[NDTOT + 1 + row] = (float)k;
            }
        }
}

// ---------------------------------------------------------------------------
// quantized output (gather) + fp64 MSE, loss finalized by last block
// ---------------------------------------------------------------------------
__global__ __launch_bounds__(256)
void quant_kernel(const float* __restrict__ x,
                  const float* __restrict__ emb,
                  float* __restrict__ out)
{
    __shared__ double sred[256];
    __shared__ bool last;
    const int total4 = NDTOT / 4;  // 1048576
    double s = 0.0;
    for (int p = blockIdx.x * 256 + threadIdx.x; p < total4; p += gridDim.x * 256) {
        int row = p >> 5, d4 = p & 31;
        int k = g_idx[row];
        float4 q  = *(const float4*)&emb[(size_t)k * DDIM + d4 * 4];
        float4 xv = *(const float4*)&x[(size_t)p * 4];
        ((float4*)out)[p] = q;
        float a = q.x - xv.x, b = q.y - xv.y, c = q.z - xv.z, d = q.w - xv.w;
        s += (double)a * a + (double)b * b + (double)c * c + (double)d * d;
    }
    sred[threadIdx.x] = s;
    __syncthreads();
    for (int o = 128; o > 0; o >>= 1) {
        if (threadIdx.x < o) sred[threadIdx.x] += sred[threadIdx.x + o];
        __syncthreads();
    }
    if (threadIdx.x == 0) {
        g_part[blockIdx.x] = sred[0];
        __threadfence();
        unsigned v = atomicAdd(&g_done, 1u);
        last = (v == 1023u);
    }
    __syncthreads();
    if (last) {
        double t = 0.0;
        for (int i = threadIdx.x; i < 1024; i += 256) t += g_part[i];
        sred[threadIdx.x] = t;
        __syncthreads();
        for (int o = 128; o > 0; o >>= 1) {
            if (threadIdx.x < o) sred[threadIdx.x] += sred[threadIdx.x + o];
            __syncthreads();
        }
        if (threadIdx.x == 0) {
            out[NDTOT] = (float)(1.25 * (sred[0] / (double)NDTOT));
            g_done = 0;   // reset for next graph replay
        }
    }
}

// ---------------------------------------------------------------------------
extern "C" void kernel_launch(void* const* d_in, const int* in_sizes, int n_in,
                              void* d_out, int out_size)
{
    const float* x   = (const float*)d_in[0];
    const float* emb = (const float*)d_in[1];
    float* out = (float*)d_out;

    cudaFuncSetAttribute(vq_argmin_mma,
                         cudaFuncAttributeMaxDynamicSharedMemorySize, SMEM_TOTAL);

    esq_kernel<<<KCODE / 8, 256>>>(emb);
    convert_emb_kernel<<<(KCODE * DDIM + 255) / 256, 256>>>(emb);
    convert_x_kernel<<<N_ROWS / 64, 256>>>(x);
    vq_argmin_mma<<<N_ROWS / 128, 128, SMEM_TOTAL>>>(out);
    quant_kernel<<<1024, 256>>>(x, emb, out);
}